// round 2
// baseline (speedup 1.0000x reference)
#include <cuda_runtime.h>

#define NH 64
#define IN_NODE 128
#define IN_EDGE 32
#define N_MAX 100000
#define E_MAX 1600000

typedef unsigned long long ull;

// ---------------- scratch (__device__ globals; no allocation) ----------------
__device__ float d_A[N_MAX * NH];      // h0 / P
__device__ float d_B[N_MAX * NH];      // h1
__device__ float d_Qb[N_MAX * NH];     // Q
__device__ int   d_cnt[N_MAX];
__device__ int   d_off[N_MAX];
__device__ int   d_cur[N_MAX];
__device__ int2  d_es[E_MAX];          // (src, edge_id) sorted by dst
__device__ float2 d_Wec2[IN_EDGE * 32];// folded We@W1c, interleaved (j, j+32)
__device__ float d_b1p[NH];
__device__ float d_w2s[NH];
__device__ float d_c2[1];

// ---------------- f32x2 helpers ----------------
__device__ __forceinline__ ull pk2(float lo, float hi) {
    ull r; asm("mov.b64 %0,{%1,%2};" : "=l"(r) : "f"(lo), "f"(hi)); return r;
}
__device__ __forceinline__ void upk2(ull v, float& lo, float& hi) {
    asm("mov.b64 {%0,%1},%2;" : "=f"(lo), "=f"(hi) : "l"(v));
}
__device__ __forceinline__ ull fma2(ull a, ull b, ull c) {
    ull d; asm("fma.rn.f32x2 %0,%1,%2,%3;" : "=l"(d) : "l"(a), "l"(b), "l"(c)); return d;
}
__device__ __forceinline__ ull dup2(float x) { return pk2(x, x); }

// ---------------- weight folding ----------------
__global__ void fold_kernel(const float* __restrict__ W1, const float* __restrict__ b1,
                            const float* __restrict__ We, const float* __restrict__ be,
                            const float* __restrict__ W2, const float* __restrict__ b2,
                            const float* __restrict__ Ws, const float* __restrict__ bs) {
    int t = threadIdx.x;
    for (int idx = t; idx < IN_EDGE * 32; idx += blockDim.x) {
        int k = idx >> 5, j = idx & 31;
        float s0 = 0.f, s1 = 0.f;
        for (int m = 0; m < NH; m++) {
            float w = We[k * NH + m];
            s0 = fmaf(w, W1[(IN_NODE + m) * NH + j], s0);
            s1 = fmaf(w, W1[(IN_NODE + m) * NH + j + 32], s1);
        }
        d_Wec2[idx] = make_float2(s0, s1);
    }
    if (t < NH) {
        float s = b1[t];
        for (int m = 0; m < NH; m++) s = fmaf(be[m], W1[(IN_NODE + m) * NH + t], s);
        d_b1p[t] = s;
        float w = 0.f;
        for (int k = 0; k < NH; k++) w = fmaf(W2[t * NH + k], Ws[k], w);
        d_w2s[t] = w;
    }
    if (t == 0) {
        float c = bs[0];
        for (int k = 0; k < NH; k++) c = fmaf(b2[k], Ws[k], c);
        d_c2[0] = c;
    }
}

// ---------------- CSR build ----------------
__global__ void zero_int_kernel(int* __restrict__ p, int n) {
    int i = blockIdx.x * blockDim.x + threadIdx.x;
    if (i < n) p[i] = 0;
}
__global__ void count_kernel(const int* __restrict__ dst, int* __restrict__ cnt, int e) {
    int i = blockIdx.x * blockDim.x + threadIdx.x;
    if (i < e) atomicAdd(&cnt[dst[i]], 1);
}
// single-block exclusive scan (n <= 1024 * chunk)
__global__ void scan_kernel(const int* __restrict__ cnt, int* __restrict__ off, int n) {
    __shared__ int ssum[1024];
    int t = threadIdx.x;
    int chunk = (n + 1023) >> 10;
    int lo = t * chunk, hi = min(lo + chunk, n);
    int s = 0;
    for (int i = lo; i < hi; i++) s += cnt[i];
    ssum[t] = s;
    __syncthreads();
    for (int d = 1; d < 1024; d <<= 1) {
        int v = (t >= d) ? ssum[t - d] : 0;
        __syncthreads();
        ssum[t] += v;
        __syncthreads();
    }
    int run = (t > 0) ? ssum[t - 1] : 0;
    for (int i = lo; i < hi; i++) { off[i] = run; run += cnt[i]; }
}
__global__ void copy_int_kernel(const int* __restrict__ a, int* __restrict__ b, int n) {
    int i = blockIdx.x * blockDim.x + threadIdx.x;
    if (i < n) b[i] = a[i];
}
__global__ void fill_kernel(const int* __restrict__ src, const int* __restrict__ dst,
                            int* __restrict__ cur, int2* __restrict__ es, int e) {
    int i = blockIdx.x * blockDim.x + threadIdx.x;
    if (i < e) {
        int d = dst[i];
        int pos = atomicAdd(&cur[d], 1);
        es[pos] = make_int2(src[i], i);
    }
}

// ---------------- node encoder: h = relu(x @ Wn + bn), 4 nodes/warp ----------------
__global__ __launch_bounds__(256) void node_enc_kernel(
    const float* __restrict__ x, const float* __restrict__ Wn,
    const float* __restrict__ bn, float* __restrict__ out, int n) {
    extern __shared__ char smraw[];
    float* sW = (float*)smraw;                       // 128*64 interleaved = 32KB
    float* sX = (float*)(smraw + 32768);             // 8 warps * 4 nodes * 128 = 16KB
    for (int i = threadIdx.x; i < IN_NODE * NH; i += 256) {
        int k = i >> 6, j = i & 63;
        sW[(k << 6) + ((j & 31) << 1) + (j >> 5)] = Wn[i];
    }
    int warp = threadIdx.x >> 5, lane = threadIdx.x & 31;
    int base = (blockIdx.x * 8 + warp) * 4;
    float* sXw = sX + warp * 4 * IN_NODE;
#pragma unroll
    for (int m = 0; m < 4; m++) {
        int nd = base + m;
        if (nd < n) {
            const float4* xr = (const float4*)(x + (size_t)nd * IN_NODE);
            ((float4*)(sXw + m * IN_NODE))[lane] = xr[lane];
        }
    }
    __syncthreads();
    const ull* sWu = (const ull*)sW;
    ull zb = pk2(bn[lane], bn[lane + 32]);
    ull z0 = zb, z1 = zb, z2 = zb, z3 = zb;
#pragma unroll 4
    for (int k0 = 0; k0 < IN_NODE; k0 += 4) {
        float4 a0 = *(const float4*)(sXw + 0 * IN_NODE + k0);
        float4 a1 = *(const float4*)(sXw + 1 * IN_NODE + k0);
        float4 a2 = *(const float4*)(sXw + 2 * IN_NODE + k0);
        float4 a3 = *(const float4*)(sXw + 3 * IN_NODE + k0);
        const float* f0 = (const float*)&a0;
        const float* f1 = (const float*)&a1;
        const float* f2 = (const float*)&a2;
        const float* f3 = (const float*)&a3;
#pragma unroll
        for (int kk = 0; kk < 4; kk++) {
            ull w = sWu[(k0 + kk) * 32 + lane];
            z0 = fma2(dup2(f0[kk]), w, z0);
            z1 = fma2(dup2(f1[kk]), w, z1);
            z2 = fma2(dup2(f2[kk]), w, z2);
            z3 = fma2(dup2(f3[kk]), w, z3);
        }
    }
    ull zz[4] = {z0, z1, z2, z3};
#pragma unroll
    for (int m = 0; m < 4; m++) {
        int nd = base + m;
        if (nd < n) {
            float lo, hi; upk2(zz[m], lo, hi);
            out[(size_t)nd * NH + lane] = fmaxf(lo, 0.f);
            out[(size_t)nd * NH + lane + 32] = fmaxf(hi, 0.f);
        }
    }
}

// ---------------- fused aggregate + SAGE combine (+ optional P/Q) ----------------
template <int DO_PQ>
__global__ __launch_bounds__(256) void combine_kernel(
    const float* __restrict__ hin, const int2* __restrict__ es,
    const int* __restrict__ off, const int* __restrict__ cnt,
    const float* __restrict__ Wl, const float* __restrict__ bl,
    const float* __restrict__ Wr, const float* __restrict__ W1,
    float* __restrict__ houtP, float* __restrict__ Qout, int n) {
    extern __shared__ char smraw[];
    float* sWl = (float*)smraw;                               // 16KB
    float* sWr = (float*)(smraw + 16384);                     // 16KB
    float* sWa = DO_PQ ? (float*)(smraw + 32768) : nullptr;   // 16KB
    float* sWb = DO_PQ ? (float*)(smraw + 49152) : nullptr;   // 16KB
    float* sRows = (float*)(smraw + (DO_PQ ? 65536 : 32768)); // sA then sH, 16KB
    float* sA = sRows;
    float* sH = sRows + 8 * 4 * NH;

    for (int i = threadIdx.x; i < NH * NH; i += 256) {
        int k = i >> 6, j = i & 63;
        int p = (k << 6) + ((j & 31) << 1) + (j >> 5);
        sWl[p] = Wl[i];
        sWr[p] = Wr[i];
        if (DO_PQ) {
            sWa[p] = W1[i];
            sWb[p] = W1[NH * NH + i];
        }
    }

    int warp = threadIdx.x >> 5, lane = threadIdx.x & 31;
    int base = (blockIdx.x * 8 + warp) * 4;

#pragma unroll
    for (int m = 0; m < 4; m++) {
        int nd = base + m;
        float a0 = 0.f, a1 = 0.f, h0 = 0.f, h1 = 0.f;
        if (nd < n) {
            int dg = cnt[nd];
            int o = off[nd];
            h0 = hin[(size_t)nd * NH + lane];
            h1 = hin[(size_t)nd * NH + lane + 32];
            int i = 0;
            for (; i + 2 <= dg; i += 2) {
                int2 e0 = es[o + i], e1 = es[o + i + 1];
                const float* r0 = hin + (size_t)e0.x * NH;
                const float* r1 = hin + (size_t)e1.x * NH;
                a0 += r0[lane]; a1 += r0[lane + 32];
                a0 += r1[lane]; a1 += r1[lane + 32];
            }
            if (i < dg) {
                const float* r0 = hin + (size_t)es[o + i].x * NH;
                a0 += r0[lane]; a1 += r0[lane + 32];
            }
            float iv = 1.f / fmaxf((float)dg, 1.f);
            a0 *= iv; a1 *= iv;
        }
        int rb = (warp * 4 + m) * NH;
        sA[rb + lane] = a0; sA[rb + lane + 32] = a1;
        sH[rb + lane] = h0; sH[rb + lane + 32] = h1;
    }
    __syncthreads();

    const ull* uWl = (const ull*)sWl;
    const ull* uWr = (const ull*)sWr;
    ull zb = pk2(bl[lane], bl[lane + 32]);
    ull z[4] = {zb, zb, zb, zb};
#pragma unroll 4
    for (int k0 = 0; k0 < NH; k0 += 4) {
        float4 av[4], hv[4];
#pragma unroll
        for (int m = 0; m < 4; m++) {
            int rb = (warp * 4 + m) * NH;
            av[m] = *(const float4*)(sA + rb + k0);
            hv[m] = *(const float4*)(sH + rb + k0);
        }
#pragma unroll
        for (int kk = 0; kk < 4; kk++) {
            ull wl = uWl[(k0 + kk) * 32 + lane];
            ull wr = uWr[(k0 + kk) * 32 + lane];
#pragma unroll
            for (int m = 0; m < 4; m++) {
                const float* af = (const float*)&av[m];
                const float* hf = (const float*)&hv[m];
                z[m] = fma2(dup2(af[kk]), wl, z[m]);
                z[m] = fma2(dup2(hf[kk]), wr, z[m]);
            }
        }
    }

    float r0[4], r1[4];
#pragma unroll
    for (int m = 0; m < 4; m++) {
        float lo, hi; upk2(z[m], lo, hi);
        r0[m] = fmaxf(lo, 0.f);
        r1[m] = fmaxf(hi, 0.f);
    }

    if (!DO_PQ) {
#pragma unroll
        for (int m = 0; m < 4; m++) {
            int nd = base + m;
            if (nd < n) {
                houtP[(size_t)nd * NH + lane] = r0[m];
                houtP[(size_t)nd * NH + lane + 32] = r1[m];
            }
        }
        return;
    }

    // stage relu(h1) rows, then P = h@W1a, Q = h@W1b
    __syncwarp();
#pragma unroll
    for (int m = 0; m < 4; m++) {
        int rb = (warp * 4 + m) * NH;
        sA[rb + lane] = r0[m];
        sA[rb + lane + 32] = r1[m];
    }
    __syncwarp();
    const ull* uWa = (const ull*)sWa;
    const ull* uWb = (const ull*)sWb;
    ull p[4] = {0, 0, 0, 0}, q[4] = {0, 0, 0, 0};
#pragma unroll 4
    for (int k0 = 0; k0 < NH; k0 += 4) {
        float4 hv[4];
#pragma unroll
        for (int m = 0; m < 4; m++)
            hv[m] = *(const float4*)(sA + (warp * 4 + m) * NH + k0);
#pragma unroll
        for (int kk = 0; kk < 4; kk++) {
            ull wa = uWa[(k0 + kk) * 32 + lane];
            ull wb = uWb[(k0 + kk) * 32 + lane];
#pragma unroll
            for (int m = 0; m < 4; m++) {
                const float* hf = (const float*)&hv[m];
                ull hd = dup2(hf[kk]);
                p[m] = fma2(hd, wa, p[m]);
                q[m] = fma2(hd, wb, q[m]);
            }
        }
    }
#pragma unroll
    for (int m = 0; m < 4; m++) {
        int nd = base + m;
        if (nd < n) {
            float lo, hi;
            upk2(p[m], lo, hi);
            houtP[(size_t)nd * NH + lane] = lo;
            houtP[(size_t)nd * NH + lane + 32] = hi;
            upk2(q[m], lo, hi);
            Qout[(size_t)nd * NH + lane] = lo;
            Qout[(size_t)nd * NH + lane + 32] = hi;
        }
    }
}

// ---------------- edge kernel: warp per dst node over CSR ----------------
__global__ __launch_bounds__(256) void edge_kernel(
    const int2* __restrict__ es, const int* __restrict__ off,
    const int* __restrict__ cnt, const float* __restrict__ ea,
    const float* __restrict__ P, const float* __restrict__ Q,
    float* __restrict__ out, int n) {
    int warp = threadIdx.x >> 5, lane = threadIdx.x & 31;
    int nd = blockIdx.x * 8 + warp;
    if (nd >= n) return;
    int dg = cnt[nd];
    if (dg == 0) return;
    int o = off[nd];

    ull wc[IN_EDGE];
    const ull* wsrc = (const ull*)d_Wec2;
#pragma unroll
    for (int k = 0; k < IN_EDGE; k++) wc[k] = wsrc[k * 32 + lane];

    ull zb = pk2(Q[(size_t)nd * NH + lane] + d_b1p[lane],
                 Q[(size_t)nd * NH + lane + 32] + d_b1p[lane + 32]);
    float ws0 = d_w2s[lane], ws1 = d_w2s[lane + 32];
    float c2 = d_c2[0];

    for (int i = 0; i < dg; i++) {
        int2 se = es[o + i];
        const float* pr = P + (size_t)se.x * NH;
        ull z = fma2(dup2(1.0f), pk2(pr[lane], pr[lane + 32]), zb);
        const float4* row = (const float4*)(ea + (size_t)se.y * IN_EDGE);
#pragma unroll
        for (int c = 0; c < 8; c++) {
            float4 v = __ldg(&row[c]);  // uniform address -> broadcast
            const float* vf = (const float*)&v;
            z = fma2(dup2(vf[0]), wc[c * 4 + 0], z);
            z = fma2(dup2(vf[1]), wc[c * 4 + 1], z);
            z = fma2(dup2(vf[2]), wc[c * 4 + 2], z);
            z = fma2(dup2(vf[3]), wc[c * 4 + 3], z);
        }
        float lo, hi; upk2(z, lo, hi);
        float v = fmaxf(lo, 0.f) * ws0 + fmaxf(hi, 0.f) * ws1;
#pragma unroll
        for (int offv = 16; offv; offv >>= 1)
            v += __shfl_down_sync(0xffffffffu, v, offv);
        if (lane == 0) out[se.y] = v + c2;
    }
}

// ---------------- launch ----------------
extern "C" void kernel_launch(void* const* d_in, const int* in_sizes, int n_in,
                              void* d_out, int out_size) {
    const float* x   = (const float*)d_in[0];
    const int* eidx  = (const int*)d_in[1];
    const float* ea  = (const float*)d_in[2];
    const float* Wn  = (const float*)d_in[3];
    const float* bn  = (const float*)d_in[4];
    const float* We  = (const float*)d_in[5];
    const float* be  = (const float*)d_in[6];
    const float* Wl0 = (const float*)d_in[7];
    const float* bl0 = (const float*)d_in[8];
    const float* Wr0 = (const float*)d_in[9];
    const float* Wl1 = (const float*)d_in[10];
    const float* bl1 = (const float*)d_in[11];
    const float* Wr1 = (const float*)d_in[12];
    const float* W1  = (const float*)d_in[13];
    const float* b1  = (const float*)d_in[14];
    const float* W2  = (const float*)d_in[15];
    const float* b2  = (const float*)d_in[16];
    const float* Ws  = (const float*)d_in[17];
    const float* bs  = (const float*)d_in[18];
    float* out = (float*)d_out;

    int n = in_sizes[0] / IN_NODE;
    int e = in_sizes[2] / IN_EDGE;
    const int* src = eidx;
    const int* dst = eidx + e;

    float *A, *B, *Q;
    int *cnt, *off, *cur;
    int2* es;
    cudaGetSymbolAddress((void**)&A, d_A);
    cudaGetSymbolAddress((void**)&B, d_B);
    cudaGetSymbolAddress((void**)&Q, d_Qb);
    cudaGetSymbolAddress((void**)&cnt, d_cnt);
    cudaGetSymbolAddress((void**)&off, d_off);
    cudaGetSymbolAddress((void**)&cur, d_cur);
    cudaGetSymbolAddress((void**)&es, d_es);

    static bool attrs_set = false;
    if (!attrs_set) {
        cudaFuncSetAttribute(node_enc_kernel, cudaFuncAttributeMaxDynamicSharedMemorySize, 49152);
        cudaFuncSetAttribute(combine_kernel<0>, cudaFuncAttributeMaxDynamicSharedMemorySize, 49152);
        cudaFuncSetAttribute(combine_kernel<1>, cudaFuncAttributeMaxDynamicSharedMemorySize, 81920);
        attrs_set = true;
    }

    int nb_n = (n + 255) / 256;
    int nb_e = (e + 255) / 256;
    int nb_w = (n + 31) / 32;   // 4 nodes/warp, 8 warps/block
    int nb_ed = (n + 7) / 8;    // warp per node

    fold_kernel<<<1, 256>>>(W1, b1, We, be, W2, b2, Ws, bs);

    // CSR build
    zero_int_kernel<<<nb_n, 256>>>(cnt, n);
    count_kernel<<<nb_e, 256>>>(dst, cnt, e);
    scan_kernel<<<1, 1024>>>(cnt, off, n);
    copy_int_kernel<<<nb_n, 256>>>(off, cur, n);
    fill_kernel<<<nb_e, 256>>>(src, dst, cur, es, e);

    // node encoder -> A
    node_enc_kernel<<<nb_w, 256, 49152>>>(x, Wn, bn, A, n);

    // layer 0: A -> B
    combine_kernel<0><<<nb_w, 256, 49152>>>(A, es, off, cnt, Wl0, bl0, Wr0, nullptr, B, nullptr, n);

    // layer 1 + PQ: B -> P(A), Q
    combine_kernel<1><<<nb_w, 256, 81920>>>(B, es, off, cnt, Wl1, bl1, Wr1, W1, A, Q, n);

    // edge output
    edge_kernel<<<nb_ed, 256>>>(es, off, cnt, ea, A, Q, out, n);
}

// round 3
// speedup vs baseline: 2.4122x; 2.4122x over previous
#include <cuda_runtime.h>

#define NH 64
#define IN_NODE 128
#define IN_EDGE 32
#define N_MAX 100000
#define E_MAX 1600000
#define SCAN_B 512

typedef unsigned long long ull;

// ---------------- scratch (__device__ globals; no allocation) ----------------
__device__ float d_A[N_MAX * NH];       // h0 / P
__device__ float d_B[N_MAX * NH];       // h1
__device__ float d_Qb[N_MAX * NH];      // Q
__device__ int   d_cnt[N_MAX];
__device__ int   d_off[N_MAX];
__device__ int   d_cur[N_MAX];
__device__ int   d_bsum[(N_MAX + SCAN_B - 1) / SCAN_B];
__device__ int   d_esrc[E_MAX];         // src sorted by dst (CSR adjacency)
__device__ float2 d_Wec2[IN_EDGE * 32]; // folded We@W1c, interleaved (j, j+32)
__device__ float d_b1p[NH];
__device__ float d_w2s[NH];
__device__ float d_c2[1];

// ---------------- f32x2 helpers ----------------
__device__ __forceinline__ ull pk2(float lo, float hi) {
    ull r; asm("mov.b64 %0,{%1,%2};" : "=l"(r) : "f"(lo), "f"(hi)); return r;
}
__device__ __forceinline__ void upk2(ull v, float& lo, float& hi) {
    asm("mov.b64 {%0,%1},%2;" : "=f"(lo), "=f"(hi) : "l"(v));
}
__device__ __forceinline__ ull fma2(ull a, ull b, ull c) {
    ull d; asm("fma.rn.f32x2 %0,%1,%2,%3;" : "=l"(d) : "l"(a), "l"(b), "l"(c)); return d;
}
__device__ __forceinline__ ull add2(ull a, ull b) {
    ull d; asm("add.rn.f32x2 %0,%1,%2;" : "=l"(d) : "l"(a), "l"(b)); return d;
}
__device__ __forceinline__ ull dup2(float x) { return pk2(x, x); }

// ---------------- weight folding ----------------
__global__ void fold_kernel(const float* __restrict__ W1, const float* __restrict__ b1,
                            const float* __restrict__ We, const float* __restrict__ be,
                            const float* __restrict__ W2, const float* __restrict__ b2,
                            const float* __restrict__ Ws, const float* __restrict__ bs) {
    int t = threadIdx.x;
    for (int idx = t; idx < IN_EDGE * 32; idx += blockDim.x) {
        int k = idx >> 5, j = idx & 31;
        float s0 = 0.f, s1 = 0.f;
        for (int m = 0; m < NH; m++) {
            float w = We[k * NH + m];
            s0 = fmaf(w, W1[(IN_NODE + m) * NH + j], s0);
            s1 = fmaf(w, W1[(IN_NODE + m) * NH + j + 32], s1);
        }
        d_Wec2[idx] = make_float2(s0, s1);
    }
    if (t < NH) {
        float s = b1[t];
        for (int m = 0; m < NH; m++) s = fmaf(be[m], W1[(IN_NODE + m) * NH + t], s);
        d_b1p[t] = s;
        float w = 0.f;
        for (int k = 0; k < NH; k++) w = fmaf(W2[t * NH + k], Ws[k], w);
        d_w2s[t] = w;
    }
    if (t == 0) {
        float c = bs[0];
        for (int k = 0; k < NH; k++) c = fmaf(b2[k], Ws[k], c);
        d_c2[0] = c;
    }
}

// ---------------- CSR build ----------------
__global__ void zero_int_kernel(int* __restrict__ p, int n) {
    int i = blockIdx.x * blockDim.x + threadIdx.x;
    if (i < n) p[i] = 0;
}
__global__ void count_kernel(const int* __restrict__ dst, int* __restrict__ cnt, int e) {
    int i = blockIdx.x * blockDim.x + threadIdx.x;
    if (i < e) atomicAdd(&cnt[dst[i]], 1);
}
// multi-block scan: per-block sums
__global__ __launch_bounds__(SCAN_B) void blocksum_kernel(
    const int* __restrict__ cnt, int* __restrict__ bsum, int n) {
    __shared__ int s[SCAN_B];
    int t = threadIdx.x;
    int i = blockIdx.x * SCAN_B + t;
    s[t] = (i < n) ? cnt[i] : 0;
    __syncthreads();
    for (int d = SCAN_B / 2; d; d >>= 1) {
        if (t < d) s[t] += s[t + d];
        __syncthreads();
    }
    if (t == 0) bsum[blockIdx.x] = s[0];
}
// single-block exclusive scan of block sums (nb <= SCAN_B)
__global__ __launch_bounds__(SCAN_B) void scansum_kernel(int* __restrict__ bsum, int nb) {
    __shared__ int s[SCAN_B];
    int t = threadIdx.x;
    int v = (t < nb) ? bsum[t] : 0;
    s[t] = v;
    __syncthreads();
    for (int d = 1; d < SCAN_B; d <<= 1) {
        int u = (t >= d) ? s[t - d] : 0;
        __syncthreads();
        s[t] += u;
        __syncthreads();
    }
    if (t < nb) bsum[t] = s[t] - v;  // exclusive
}
// per-block exclusive scan + block prefix -> off (and cur copy)
__global__ __launch_bounds__(SCAN_B) void scanfin_kernel(
    const int* __restrict__ cnt, const int* __restrict__ bsum,
    int* __restrict__ off, int* __restrict__ cur, int n) {
    __shared__ int s[SCAN_B];
    int t = threadIdx.x;
    int i = blockIdx.x * SCAN_B + t;
    int v = (i < n) ? cnt[i] : 0;
    s[t] = v;
    __syncthreads();
    for (int d = 1; d < SCAN_B; d <<= 1) {
        int u = (t >= d) ? s[t - d] : 0;
        __syncthreads();
        s[t] += u;
        __syncthreads();
    }
    if (i < n) {
        int o = s[t] - v + bsum[blockIdx.x];
        off[i] = o;
        cur[i] = o;
    }
}
__global__ void fill_kernel(const int* __restrict__ src, const int* __restrict__ dst,
                            int* __restrict__ cur, int* __restrict__ esrc, int e) {
    int i = blockIdx.x * blockDim.x + threadIdx.x;
    if (i < e) {
        int pos = atomicAdd(&cur[dst[i]], 1);
        esrc[pos] = src[i];
    }
}

// ---------------- node encoder: h = relu(x @ Wn + bn), 4 nodes/warp ----------------
__global__ __launch_bounds__(256) void node_enc_kernel(
    const float* __restrict__ x, const float* __restrict__ Wn,
    const float* __restrict__ bn, float* __restrict__ out, int n) {
    extern __shared__ char smraw[];
    float* sW = (float*)smraw;            // 32KB interleaved
    float* sX = (float*)(smraw + 32768);  // 16KB
    for (int i = threadIdx.x; i < IN_NODE * NH; i += 256) {
        int k = i >> 6, j = i & 63;
        sW[(k << 6) + ((j & 31) << 1) + (j >> 5)] = Wn[i];
    }
    int warp = threadIdx.x >> 5, lane = threadIdx.x & 31;
    int base = (blockIdx.x * 8 + warp) * 4;
    float* sXw = sX + warp * 4 * IN_NODE;
#pragma unroll
    for (int m = 0; m < 4; m++) {
        int nd = base + m;
        if (nd < n) {
            const float4* xr = (const float4*)(x + (size_t)nd * IN_NODE);
            ((float4*)(sXw + m * IN_NODE))[lane] = xr[lane];
        }
    }
    __syncthreads();
    const ull* sWu = (const ull*)sW;
    ull zb = pk2(bn[lane], bn[lane + 32]);
    ull z0 = zb, z1 = zb, z2 = zb, z3 = zb;
#pragma unroll 4
    for (int k0 = 0; k0 < IN_NODE; k0 += 4) {
        float4 a0 = *(const float4*)(sXw + 0 * IN_NODE + k0);
        float4 a1 = *(const float4*)(sXw + 1 * IN_NODE + k0);
        float4 a2 = *(const float4*)(sXw + 2 * IN_NODE + k0);
        float4 a3 = *(const float4*)(sXw + 3 * IN_NODE + k0);
        const float* f0 = (const float*)&a0;
        const float* f1 = (const float*)&a1;
        const float* f2 = (const float*)&a2;
        const float* f3 = (const float*)&a3;
#pragma unroll
        for (int kk = 0; kk < 4; kk++) {
            ull w = sWu[(k0 + kk) * 32 + lane];
            z0 = fma2(dup2(f0[kk]), w, z0);
            z1 = fma2(dup2(f1[kk]), w, z1);
            z2 = fma2(dup2(f2[kk]), w, z2);
            z3 = fma2(dup2(f3[kk]), w, z3);
        }
    }
    ull zz[4] = {z0, z1, z2, z3};
#pragma unroll
    for (int m = 0; m < 4; m++) {
        int nd = base + m;
        if (nd < n) {
            float lo, hi; upk2(zz[m], lo, hi);
            out[(size_t)nd * NH + lane] = fmaxf(lo, 0.f);
            out[(size_t)nd * NH + lane + 32] = fmaxf(hi, 0.f);
        }
    }
}

// ---------------- fused aggregate + SAGE combine (+ optional fused P/Q) ----------------
// smem: sW0(16KB) | sW1s(16KB) | sA(8KB) | sH(8KB)  = 48KB for both variants
template <int DO_PQ>
__global__ __launch_bounds__(256) void combine_kernel(
    const float* __restrict__ hin, const int* __restrict__ esrc,
    const int* __restrict__ off, const int* __restrict__ cnt,
    const float* __restrict__ Wl, const float* __restrict__ bl,
    const float* __restrict__ Wr, const float* __restrict__ W1,
    float* __restrict__ houtP, float* __restrict__ Qout, int n) {
    extern __shared__ char smraw[];
    float* sW0 = (float*)smraw;              // Wl, later W1a
    float* sW1s = (float*)(smraw + 16384);   // Wr, later W1b
    float* sA = (float*)(smraw + 32768);     // agg rows, later relu(h) rows
    float* sH = (float*)(smraw + 40960);     // self rows

    for (int i = threadIdx.x; i < NH * NH; i += 256) {
        int k = i >> 6, j = i & 63;
        int p = (k << 6) + ((j & 31) << 1) + (j >> 5);
        sW0[p] = Wl[i];
        sW1s[p] = Wr[i];
    }

    int warp = threadIdx.x >> 5, lane = threadIdx.x & 31;
    int base = (blockIdx.x * 8 + warp) * 4;

#pragma unroll
    for (int m = 0; m < 4; m++) {
        int nd = base + m;
        float a0 = 0.f, a1 = 0.f, h0 = 0.f, h1 = 0.f;
        if (nd < n) {
            int dg = cnt[nd];
            int o = off[nd];
            h0 = __ldg(hin + (size_t)nd * NH + lane);
            h1 = __ldg(hin + (size_t)nd * NH + lane + 32);
            int i = 0;
            for (; i + 4 <= dg; i += 4) {
                int s0 = __ldg(esrc + o + i);
                int s1 = __ldg(esrc + o + i + 1);
                int s2 = __ldg(esrc + o + i + 2);
                int s3 = __ldg(esrc + o + i + 3);
                const float* r0 = hin + (size_t)s0 * NH;
                const float* r1 = hin + (size_t)s1 * NH;
                const float* r2 = hin + (size_t)s2 * NH;
                const float* r3 = hin + (size_t)s3 * NH;
                float x0 = __ldg(r0 + lane), y0 = __ldg(r0 + lane + 32);
                float x1 = __ldg(r1 + lane), y1 = __ldg(r1 + lane + 32);
                float x2 = __ldg(r2 + lane), y2 = __ldg(r2 + lane + 32);
                float x3 = __ldg(r3 + lane), y3 = __ldg(r3 + lane + 32);
                a0 += (x0 + x1) + (x2 + x3);
                a1 += (y0 + y1) + (y2 + y3);
            }
            for (; i < dg; i++) {
                const float* r0 = hin + (size_t)__ldg(esrc + o + i) * NH;
                a0 += __ldg(r0 + lane);
                a1 += __ldg(r0 + lane + 32);
            }
            float iv = 1.f / fmaxf((float)dg, 1.f);
            a0 *= iv; a1 *= iv;
        }
        int rb = (warp * 4 + m) * NH;
        sA[rb + lane] = a0; sA[rb + lane + 32] = a1;
        sH[rb + lane] = h0; sH[rb + lane + 32] = h1;
    }
    __syncthreads();

    const ull* uWl = (const ull*)sW0;
    const ull* uWr = (const ull*)sW1s;
    ull zb = pk2(bl[lane], bl[lane + 32]);
    ull z[4] = {zb, zb, zb, zb};
#pragma unroll 4
    for (int k0 = 0; k0 < NH; k0 += 4) {
        float4 av[4], hv[4];
#pragma unroll
        for (int m = 0; m < 4; m++) {
            int rb = (warp * 4 + m) * NH;
            av[m] = *(const float4*)(sA + rb + k0);
            hv[m] = *(const float4*)(sH + rb + k0);
        }
#pragma unroll
        for (int kk = 0; kk < 4; kk++) {
            ull wl = uWl[(k0 + kk) * 32 + lane];
            ull wr = uWr[(k0 + kk) * 32 + lane];
#pragma unroll
            for (int m = 0; m < 4; m++) {
                const float* af = (const float*)&av[m];
                const float* hf = (const float*)&hv[m];
                z[m] = fma2(dup2(af[kk]), wl, z[m]);
                z[m] = fma2(dup2(hf[kk]), wr, z[m]);
            }
        }
    }

    float r0[4], r1[4];
#pragma unroll
    for (int m = 0; m < 4; m++) {
        float lo, hi; upk2(z[m], lo, hi);
        r0[m] = fmaxf(lo, 0.f);
        r1[m] = fmaxf(hi, 0.f);
    }

    if (!DO_PQ) {
#pragma unroll
        for (int m = 0; m < 4; m++) {
            int nd = base + m;
            if (nd < n) {
                houtP[(size_t)nd * NH + lane] = r0[m];
                houtP[(size_t)nd * NH + lane + 32] = r1[m];
            }
        }
        return;
    }

    // -------- fused P/Q: reuse weight smem (all warps done with Wl/Wr) --------
    __syncthreads();
    for (int i = threadIdx.x; i < NH * NH; i += 256) {
        int k = i >> 6, j = i & 63;
        int p = (k << 6) + ((j & 31) << 1) + (j >> 5);
        sW0[p] = W1[i];
        sW1s[p] = W1[NH * NH + i];
    }
#pragma unroll
    for (int m = 0; m < 4; m++) {
        int rb = (warp * 4 + m) * NH;
        sA[rb + lane] = r0[m];
        sA[rb + lane + 32] = r1[m];
    }
    __syncthreads();

    const ull* uWa = (const ull*)sW0;
    const ull* uWb = (const ull*)sW1s;
    ull p[4] = {0, 0, 0, 0}, q[4] = {0, 0, 0, 0};
#pragma unroll 4
    for (int k0 = 0; k0 < NH; k0 += 4) {
        float4 hv[4];
#pragma unroll
        for (int m = 0; m < 4; m++)
            hv[m] = *(const float4*)(sA + (warp * 4 + m) * NH + k0);
#pragma unroll
        for (int kk = 0; kk < 4; kk++) {
            ull wa = uWa[(k0 + kk) * 32 + lane];
            ull wb = uWb[(k0 + kk) * 32 + lane];
#pragma unroll
            for (int m = 0; m < 4; m++) {
                const float* hf = (const float*)&hv[m];
                ull hd = dup2(hf[kk]);
                p[m] = fma2(hd, wa, p[m]);
                q[m] = fma2(hd, wb, q[m]);
            }
        }
    }
#pragma unroll
    for (int m = 0; m < 4; m++) {
        int nd = base + m;
        if (nd < n) {
            float lo, hi;
            upk2(p[m], lo, hi);
            houtP[(size_t)nd * NH + lane] = lo;
            houtP[(size_t)nd * NH + lane + 32] = hi;
            upk2(q[m], lo, hi);
            Qout[(size_t)nd * NH + lane] = lo;
            Qout[(size_t)nd * NH + lane + 32] = hi;
        }
    }
}

// ---------------- edge kernel: streamed 256-edge tiles, warp per 32 edges ----------------
#define ETILE 256
__global__ __launch_bounds__(256) void edge_kernel(
    const int* __restrict__ src, const int* __restrict__ dst,
    const float* __restrict__ ea, const float* __restrict__ P,
    const float* __restrict__ Q, float* __restrict__ out, int e) {
    __shared__ float sEA[ETILE * IN_EDGE];  // 32KB
    __shared__ int sS[ETILE];
    __shared__ int sD[ETILE];
    int t = threadIdx.x, warp = t >> 5, lane = t & 31;
    int base = blockIdx.x * ETILE;
    int cnt = min(ETILE, e - base);

    // folded edge weights in registers (interleaved f32x2 columns)
    ull wc[IN_EDGE];
    const ull* wsrc = (const ull*)d_Wec2;
#pragma unroll
    for (int k = 0; k < IN_EDGE; k++) wc[k] = wsrc[k * 32 + lane];
    ull zb = pk2(d_b1p[lane], d_b1p[lane + 32]);
    float ws0 = d_w2s[lane], ws1 = d_w2s[lane + 32];
    float c2 = d_c2[0];

    // coalesced stage of edge_attr tile + endpoints
    const float4* eag = (const float4*)(ea + (size_t)base * IN_EDGE);
    float4* eas = (float4*)sEA;
    int n4 = cnt * (IN_EDGE / 4);
    for (int i = t; i < n4; i += 256) eas[i] = eag[i];
    for (int i = t; i < cnt; i += 256) {
        sS[i] = src[base + i];
        sD[i] = dst[base + i];
    }
    __syncthreads();

    int e0 = warp * 32;
    int e1 = min(e0 + 32, cnt);
#pragma unroll 4
    for (int j = e0; j < e1; j++) {
        int s = sS[j], d = sD[j];
        const float* pr = P + (size_t)s * NH;
        const float* qr = Q + (size_t)d * NH;
        float zlo = __ldg(pr + lane) + __ldg(qr + lane);
        float zhi = __ldg(pr + lane + 32) + __ldg(qr + lane + 32);
        ull z = add2(pk2(zlo, zhi), zb);
        const float4* row = (const float4*)(sEA + j * IN_EDGE);
#pragma unroll
        for (int c = 0; c < 8; c++) {
            float4 v = row[c];  // uniform smem -> broadcast
            const float* vf = (const float*)&v;
            z = fma2(dup2(vf[0]), wc[c * 4 + 0], z);
            z = fma2(dup2(vf[1]), wc[c * 4 + 1], z);
            z = fma2(dup2(vf[2]), wc[c * 4 + 2], z);
            z = fma2(dup2(vf[3]), wc[c * 4 + 3], z);
        }
        float lo, hi; upk2(z, lo, hi);
        float v = fmaxf(lo, 0.f) * ws0 + fmaxf(hi, 0.f) * ws1;
#pragma unroll
        for (int o = 16; o; o >>= 1) v += __shfl_down_sync(0xffffffffu, v, o);
        if (lane == 0) out[base + j] = v + c2;
    }
}

// ---------------- launch ----------------
extern "C" void kernel_launch(void* const* d_in, const int* in_sizes, int n_in,
                              void* d_out, int out_size) {
    const float* x   = (const float*)d_in[0];
    const int* eidx  = (const int*)d_in[1];
    const float* ea  = (const float*)d_in[2];
    const float* Wn  = (const float*)d_in[3];
    const float* bn  = (const float*)d_in[4];
    const float* We  = (const float*)d_in[5];
    const float* be  = (const float*)d_in[6];
    const float* Wl0 = (const float*)d_in[7];
    const float* bl0 = (const float*)d_in[8];
    const float* Wr0 = (const float*)d_in[9];
    const float* Wl1 = (const float*)d_in[10];
    const float* bl1 = (const float*)d_in[11];
    const float* Wr1 = (const float*)d_in[12];
    const float* W1  = (const float*)d_in[13];
    const float* b1  = (const float*)d_in[14];
    const float* W2  = (const float*)d_in[15];
    const float* b2  = (const float*)d_in[16];
    const float* Ws  = (const float*)d_in[17];
    const float* bs  = (const float*)d_in[18];
    float* out = (float*)d_out;

    int n = in_sizes[0] / IN_NODE;
    int e = in_sizes[2] / IN_EDGE;
    const int* src = eidx;
    const int* dst = eidx + e;

    float *A, *B, *Q;
    int *cnt, *off, *cur, *bsum, *esrc;
    cudaGetSymbolAddress((void**)&A, d_A);
    cudaGetSymbolAddress((void**)&B, d_B);
    cudaGetSymbolAddress((void**)&Q, d_Qb);
    cudaGetSymbolAddress((void**)&cnt, d_cnt);
    cudaGetSymbolAddress((void**)&off, d_off);
    cudaGetSymbolAddress((void**)&cur, d_cur);
    cudaGetSymbolAddress((void**)&bsum, d_bsum);
    cudaGetSymbolAddress((void**)&esrc, d_esrc);

    static bool attrs_set = false;
    if (!attrs_set) {
        cudaFuncSetAttribute(node_enc_kernel, cudaFuncAttributeMaxDynamicSharedMemorySize, 49152);
        cudaFuncSetAttribute(combine_kernel<0>, cudaFuncAttributeMaxDynamicSharedMemorySize, 49152);
        cudaFuncSetAttribute(combine_kernel<1>, cudaFuncAttributeMaxDynamicSharedMemorySize, 49152);
        attrs_set = true;
    }

    int nb_n = (n + 255) / 256;
    int nb_e = (e + 255) / 256;
    int nb_w = (n + 31) / 32;            // combine: 4 nodes/warp, 8 warps/block
    int nb_sc = (n + SCAN_B - 1) / SCAN_B;
    int nb_ed = (e + ETILE - 1) / ETILE;

    fold_kernel<<<1, 256>>>(W1, b1, We, be, W2, b2, Ws, bs);

    // CSR build
    zero_int_kernel<<<nb_n, 256>>>(cnt, n);
    count_kernel<<<nb_e, 256>>>(dst, cnt, e);
    blocksum_kernel<<<nb_sc, SCAN_B>>>(cnt, bsum, n);
    scansum_kernel<<<1, SCAN_B>>>(bsum, nb_sc);
    scanfin_kernel<<<nb_sc, SCAN_B>>>(cnt, bsum, off, cur, n);
    fill_kernel<<<nb_e, 256>>>(src, dst, cur, esrc, e);

    // node encoder -> A
    node_enc_kernel<<<nb_w, 256, 49152>>>(x, Wn, bn, A, n);

    // layer 0: A -> B
    combine_kernel<0><<<nb_w, 256, 49152>>>(A, esrc, off, cnt, Wl0, bl0, Wr0, nullptr, B, nullptr, n);

    // layer 1 + fused PQ: B -> P(A), Q
    combine_kernel<1><<<nb_w, 256, 49152>>>(B, esrc, off, cnt, Wl1, bl1, Wr1, W1, A, Q, n);

    // edge output (natural order, streamed ea)
    edge_kernel<<<nb_ed, 256>>>(src, dst, ea, A, Q, out, e);
}